// round 3
// baseline (speedup 1.0000x reference)
#include <cuda_runtime.h>
#include <cstddef>

#define C_DIM 64
#define H_DIM 150000
#define K_DIM 27
#define TILE_H 32
#define NBLK_H ((H_DIM + TILE_H - 1) / TILE_H)   // 4688

// Scratch: node-major x (x_t[h][c]) and k-major neigh (nt[k][h]).
__device__ float g_xt[(size_t)H_DIM * C_DIM];   // 38.4 MB
__device__ int   g_nt[(size_t)K_DIM * H_DIM];   // 16.2 MB

// ---------------------------------------------------------------------------
// Transpose x: (C, H) -> (H, C). 32h x 32c tile, block (32,8).
// ---------------------------------------------------------------------------
__global__ __launch_bounds__(256) void transpose_x_kernel(const float* __restrict__ x) {
    __shared__ float tile[32][33];
    const int hb = blockIdx.x * 32;
    const int cb = blockIdx.y * 32;
    const int tx = threadIdx.x, ty = threadIdx.y;

    const int h = hb + tx;
    if (h < H_DIM) {
        #pragma unroll
        for (int i = 0; i < 4; ++i) {
            const int c = cb + ty * 4 + i;
            tile[ty * 4 + i][tx] = x[(size_t)c * H_DIM + h];
        }
    }
    __syncthreads();

    const int j   = ty * 32 + tx;
    const int row = j / 8;
    const int cg  = j % 8;
    const int hh  = hb + row;
    if (hh < H_DIM) {
        float4 v = make_float4(tile[cg * 4 + 0][row], tile[cg * 4 + 1][row],
                               tile[cg * 4 + 2][row], tile[cg * 4 + 3][row]);
        *reinterpret_cast<float4*>(&g_xt[(size_t)hh * C_DIM + cb + cg * 4]) = v;
    }
}

// ---------------------------------------------------------------------------
// Transpose neigh: (H, K) -> (K, H).
// ---------------------------------------------------------------------------
__global__ void transpose_n_kernel(const int* __restrict__ nb) {
    __shared__ int tile[32][33];
    const int hb = blockIdx.x * 32;
    const int tx = threadIdx.x, ty = threadIdx.y;

    const int h_in = hb + ty;
    if (h_in < H_DIM && tx < K_DIM)
        tile[ty][tx] = nb[(size_t)h_in * K_DIM + tx];
    __syncthreads();

    const int h_out = hb + tx;
    if (h_out < H_DIM && ty < K_DIM)
        g_nt[(size_t)ty * H_DIM + h_out] = tile[tx][ty];
}

// ---------------------------------------------------------------------------
// Warp-cooperative gather via swizzled smem staging.
// Block = 32 nodes (h) x 64 channels for one k.
//   Load phase:  16 lanes cooperate on one 256B node row -> 4 wf per warp-LDG.
//   smem layout: logical (node j, chunk q of 4 floats) stored at physical
//                chunk p = q ^ (j & 15)  (conflict-free STS.128 phases).
//   Store phase: warp = 32 h for one channel c, coalesced STG.32 (__stcs).
// ---------------------------------------------------------------------------
__global__ __launch_bounds__(256) void gather_kernel(float* __restrict__ out) {
    __shared__ float sm[TILE_H * C_DIM];   // 8 KB, swizzled
    __shared__ int   nidx[TILE_H];

    const int t  = threadIdx.x;
    const int k  = blockIdx.y;
    const int hb = blockIdx.x * TILE_H;

    // --- index load (coalesced from k-major neigh) ---
    if (t < TILE_H) {
        const int h = hb + t;
        nidx[t] = (h < H_DIM) ? g_nt[(size_t)k * H_DIM + h] : -1;
    }
    __syncthreads();

    // --- gather phase: 512 float4 chunks (32 nodes x 16 chunks), 2 rounds ---
    #pragma unroll
    for (int r = 0; r < 2; ++r) {
        const int id = r * 256 + t;
        const int j  = id >> 4;          // node within tile
        const int q  = id & 15;          // logical channel chunk
        const int node = nidx[j];
        float4 v = make_float4(0.f, 0.f, 0.f, 0.f);
        if (node >= 0)
            v = *reinterpret_cast<const float4*>(&g_xt[(size_t)node * C_DIM + q * 4]);
        const int p = q ^ (j & 15);      // swizzled physical chunk
        *reinterpret_cast<float4*>(&sm[j * C_DIM + p * 4]) = v;
    }
    __syncthreads();

    // --- store phase: 2048 floats (64 c x 32 h), 8 rounds of STG.32 ---
    const size_t KH = (size_t)K_DIM * H_DIM;
    #pragma unroll
    for (int r = 0; r < 8; ++r) {
        const int id = r * 256 + t;
        const int c  = id >> 5;          // channel
        const int h  = id & 31;          // node within tile (== lane)
        const int p  = (c >> 2) ^ (h & 15);
        const float val = sm[h * C_DIM + p * 4 + (c & 3)];
        const int hh = hb + h;
        if (hh < H_DIM)
            __stcs(&out[(size_t)c * KH + (size_t)k * H_DIM + hh], val);
    }
}

extern "C" void kernel_launch(void* const* d_in, const int* in_sizes, int n_in,
                              void* d_out, int out_size) {
    const float* x   = (const float*)d_in[0];   // (1, 64, 150000, 1) fp32
    const int*   nb  = (const int*)d_in[1];     // (150000, 27) int32
    float*       out = (float*)d_out;           // (1, 64, 27, 150000) fp32

    (void)in_sizes; (void)n_in; (void)out_size;

    {
        dim3 block(32, 8);
        dim3 grid((H_DIM + 31) / 32, C_DIM / 32);
        transpose_x_kernel<<<grid, block>>>(x);
    }
    {
        dim3 block(32, 32);
        dim3 grid((H_DIM + 31) / 32, 1);
        transpose_n_kernel<<<grid, block>>>(nb);
    }
    {
        dim3 block(256);
        dim3 grid(NBLK_H, K_DIM);
        gather_kernel<<<grid, block>>>(out);
    }
}